// round 8
// baseline (speedup 1.0000x reference)
#include <cuda_runtime.h>
#include <cuda_fp16.h>
#include <math.h>
#include <stdint.h>

#define NN 50000
#define DD 128
#define EE 800000
#define FULL 0xffffffffu

// ---------------- scratch (device globals; no allocation) ----------------
__device__ __align__(16) __half g_hs0[NN * DD];
__device__ __align__(16) __half g_hs1[NN * DD];
__device__ __align__(16) float g_hfood[NN * DD];
__device__ __align__(16) float g_hnut[NN * DD];
__device__ __align__(16) float g_as0[NN * 4];
__device__ __align__(16) float g_as1[NN * 4];
__device__ __align__(16) float g_ad0[NN * 4];
__device__ __align__(16) float g_ad1[NN * 4];
__device__ __align__(16) float g_Ad0[DD * 4];
__device__ __align__(16) float g_Ad1[DD * 4];
__device__ __align__(16) float g_w0[EE * 4];
__device__ __align__(16) float g_w1[EE * 4];
__device__ int g_off0[NN + 1];
__device__ int g_off1[NN + 1];
__device__ int g_cur0[NN];
__device__ int g_cur1[NN];
__device__ int g_csr0[EE];
__device__ int g_csr1[EE];

__device__ __forceinline__ float lrelu(float x) { return x > 0.f ? x : 0.2f * x; }
__device__ __forceinline__ float eluf(float x) { return x > 0.f ? x : expm1f(x); }

// ---------------- fused GEMM + alpha_s epilogue (fp16 Y), sw-pipelined ------
// Y[N,128](fp16) = X[N,128] @ W[128,128]
// AS[n,h] = sum_c Yf32[n, h*32+c] * att[h*32+c]
// block: 256 threads = 16x16, each thread 8x8. Tile 128 rows x 128 cols.
// grid: (391, 2) -- blockIdx.y selects relation.
__global__ __launch_bounds__(256, 2) void gemm_fused(
    const float* __restrict__ X0, const float* __restrict__ X1,
    const float* __restrict__ W0, const float* __restrict__ W1,
    const float* __restrict__ att0, const float* __restrict__ att1,
    __half* __restrict__ Y0, __half* __restrict__ Y1,
    float* __restrict__ AS0, float* __restrict__ AS1) {
    int rel = blockIdx.y;
    const float* __restrict__ X   = rel ? X1 : X0;
    const float* __restrict__ W   = rel ? W1 : W0;
    const float* __restrict__ att = rel ? att1 : att0;
    __half* __restrict__ Y  = rel ? Y1 : Y0;
    float* __restrict__ AS  = rel ? AS1 : AS0;

    __shared__ float Xs[16][128];
    __shared__ float Ws[16][128];

    int tid = threadIdx.x;
    int tx = tid & 15, ty = tid >> 4;
    int rowBase = blockIdx.x * 128;
    int r0 = ty * 8, c0 = tx * 8;

    float acc[8][8];
#pragma unroll
    for (int i = 0; i < 8; i++)
#pragma unroll
        for (int j = 0; j < 8; j++) acc[i][j] = 0.f;

    int xrow = tid & 127;
    int xk4  = (tid >> 7) * 8;       // 0 or 8
    int grow = rowBase + xrow;
    bool xvalid = grow < NN;
    const float* Xbase = X + (size_t)grow * DD;
    int wk = tid >> 4;               // 0..15
    int wc = (tid & 15) * 8;

    // prologue loads (k0 = 0)
    float4 a0 = xvalid ? *(const float4*)(Xbase + xk4) : make_float4(0.f, 0.f, 0.f, 0.f);
    float4 a1 = xvalid ? *(const float4*)(Xbase + xk4 + 4) : make_float4(0.f, 0.f, 0.f, 0.f);
    float4 b0 = *(const float4*)(W + (size_t)wk * DD + wc);
    float4 b1 = *(const float4*)(W + (size_t)wk * DD + wc + 4);

#pragma unroll
    for (int k0 = 0; k0 < 128; k0 += 16) {
        __syncthreads();
        Xs[xk4 + 0][xrow] = a0.x; Xs[xk4 + 1][xrow] = a0.y;
        Xs[xk4 + 2][xrow] = a0.z; Xs[xk4 + 3][xrow] = a0.w;
        Xs[xk4 + 4][xrow] = a1.x; Xs[xk4 + 5][xrow] = a1.y;
        Xs[xk4 + 6][xrow] = a1.z; Xs[xk4 + 7][xrow] = a1.w;
        *(float4*)&Ws[wk][wc]     = b0;
        *(float4*)&Ws[wk][wc + 4] = b1;
        __syncthreads();
        // prefetch next k-step; LDG retires under the FFMA block below
        if (k0 + 16 < 128) {
            int kn = k0 + 16;
            a0 = xvalid ? *(const float4*)(Xbase + kn + xk4) : make_float4(0.f, 0.f, 0.f, 0.f);
            a1 = xvalid ? *(const float4*)(Xbase + kn + xk4 + 4) : make_float4(0.f, 0.f, 0.f, 0.f);
            b0 = *(const float4*)(W + (size_t)(kn + wk) * DD + wc);
            b1 = *(const float4*)(W + (size_t)(kn + wk) * DD + wc + 4);
        }
#pragma unroll
        for (int kk = 0; kk < 16; kk++) {
            float xr[8], wr[8];
            *(float4*)(xr)     = *(const float4*)&Xs[kk][r0];
            *(float4*)(xr + 4) = *(const float4*)&Xs[kk][r0 + 4];
            *(float4*)(wr)     = *(const float4*)&Ws[kk][c0];
            *(float4*)(wr + 4) = *(const float4*)&Ws[kk][c0 + 4];
#pragma unroll
            for (int i = 0; i < 8; i++)
#pragma unroll
                for (int j = 0; j < 8; j++) acc[i][j] += xr[i] * wr[j];
        }
    }

    // epilogue: store Y (fp16) and fused alpha_s
    float av[8];
#pragma unroll
    for (int j = 0; j < 8; j++) av[j] = att[c0 + j];
    int h = tx >> 2;
#pragma unroll
    for (int i = 0; i < 8; i++) {
        int gr = rowBase + r0 + i;
        if (gr < NN) {
            __half2 hh[4];
            hh[0] = __floats2half2_rn(acc[i][0], acc[i][1]);
            hh[1] = __floats2half2_rn(acc[i][2], acc[i][3]);
            hh[2] = __floats2half2_rn(acc[i][4], acc[i][5]);
            hh[3] = __floats2half2_rn(acc[i][6], acc[i][7]);
            *(uint4*)(Y + (size_t)gr * DD + c0) = *(uint4*)hh;
        }
        float p = acc[i][0] * av[0] + acc[i][1] * av[1] + acc[i][2] * av[2] +
                  acc[i][3] * av[3] + acc[i][4] * av[4] + acc[i][5] * av[5] +
                  acc[i][6] * av[6] + acc[i][7] * av[7];
        p += __shfl_xor_sync(FULL, p, 1);
        p += __shfl_xor_sync(FULL, p, 2);
        if ((tx & 3) == 0 && gr < NN) AS[(size_t)gr * 4 + h] = p;
    }
}

// ---------------- Avec: Ad[d,h] = sum_c Wdst[d, h*32+c] * att[h,c] ----------------
__global__ void avec2(const float* __restrict__ Wd0, const float* __restrict__ Wd1,
                      const float* __restrict__ at0, const float* __restrict__ at1,
                      float* __restrict__ Ad0, float* __restrict__ Ad1) {
    int rel = blockIdx.x;
    const float* W = rel ? Wd1 : Wd0;
    const float* att = rel ? at1 : at0;
    float* out = rel ? Ad1 : Ad0;
    int d = threadIdx.x;
#pragma unroll
    for (int hh = 0; hh < 4; hh++) {
        float s = 0.f;
#pragma unroll
        for (int c = 0; c < 32; c++) s += W[d * 128 + hh * 32 + c] * att[hh * 32 + c];
        out[d * 4 + hh] = s;
    }
}

// ---------------- alpha_d[n,h] = xd[n,:] @ Ad[:,h] (warp per node) ----------------
__global__ __launch_bounds__(256) void alpha2(const float* __restrict__ xd0,
                                              const float* __restrict__ xd1,
                                              const float* __restrict__ Ad0,
                                              const float* __restrict__ Ad1,
                                              float* __restrict__ out0,
                                              float* __restrict__ out1) {
    int rel = blockIdx.y;
    const float* x = rel ? xd1 : xd0;
    const float* avec = rel ? Ad1 : Ad0;
    float* alpha = rel ? out1 : out0;
    int wid = (blockIdx.x * blockDim.x + threadIdx.x) >> 5;
    int lane = threadIdx.x & 31;
    if (wid >= NN) return;
    float p0 = 0.f, p1 = 0.f, p2 = 0.f, p3 = 0.f;
#pragma unroll
    for (int j = 0; j < 4; j++) {
        int d = lane + j * 32;
        float xv = x[(size_t)wid * DD + d];
        float4 av = *(const float4*)(avec + d * 4);
        p0 += xv * av.x; p1 += xv * av.y; p2 += xv * av.z; p3 += xv * av.w;
    }
#pragma unroll
    for (int o = 16; o; o >>= 1) {
        p0 += __shfl_xor_sync(FULL, p0, o);
        p1 += __shfl_xor_sync(FULL, p1, o);
        p2 += __shfl_xor_sync(FULL, p2, o);
        p3 += __shfl_xor_sync(FULL, p3, o);
    }
    if (lane == 0) *(float4*)(alpha + (size_t)wid * 4) = make_float4(p0, p1, p2, p3);
}

// ---------------- CSR build (fused over both relations) ----------------
__global__ void zero2(int* __restrict__ a, int* __restrict__ b, int n) {
    for (int i = blockIdx.x * blockDim.x + threadIdx.x; i < n; i += gridDim.x * blockDim.x) {
        a[i] = 0; b[i] = 0;
    }
}
__global__ void hist2(const int* __restrict__ d0, const int* __restrict__ d1,
                      int* __restrict__ c0, int* __restrict__ c1, int n) {
    for (int i = blockIdx.x * blockDim.x + threadIdx.x; i < n; i += gridDim.x * blockDim.x) {
        atomicAdd(&c0[d0[i] + 1], 1);
        atomicAdd(&c1[d1[i] + 1], 1);
    }
}
// scan + cursor init fused (cursor gets the same prefix values)
__global__ __launch_bounds__(1024) void scan2(int* __restrict__ a0, int* __restrict__ a1,
                                              int* __restrict__ cur0, int* __restrict__ cur1,
                                              int n) {
    int* a = blockIdx.x ? a1 : a0;
    int* cur = blockIdx.x ? cur1 : cur0;
    __shared__ int warpsum[32];
    __shared__ int carry_s;
    int tid = threadIdx.x, lane = tid & 31, w = tid >> 5;
    if (tid == 0) carry_s = 0;
    __syncthreads();
    for (int base = 0; base < n; base += 1024) {
        int idx = base + tid;
        int v = (idx < n) ? a[idx] : 0;
        int x = v;
#pragma unroll
        for (int o = 1; o < 32; o <<= 1) {
            int t = __shfl_up_sync(FULL, x, o);
            if (lane >= o) x += t;
        }
        if (lane == 31) warpsum[w] = x;
        __syncthreads();
        if (w == 0) {
            int y = warpsum[lane];
#pragma unroll
            for (int o = 1; o < 32; o <<= 1) {
                int t = __shfl_up_sync(FULL, y, o);
                if (lane >= o) y += t;
            }
            warpsum[lane] = y;
        }
        __syncthreads();
        int incl = x + (w > 0 ? warpsum[w - 1] : 0);
        int carry = carry_s;
        if (idx < n) {
            int val = carry + incl;
            a[idx] = val;
            if (idx < NN) cur[idx] = val;
        }
        __syncthreads();
        if (tid == 1023) carry_s = carry + warpsum[31];
        __syncthreads();
    }
}
__global__ void fill2(const int* __restrict__ e0, const int* __restrict__ e1,
                      int* __restrict__ cu0, int* __restrict__ cu1,
                      int* __restrict__ cs0, int* __restrict__ cs1, int n) {
    for (int i = blockIdx.x * blockDim.x + threadIdx.x; i < n; i += gridDim.x * blockDim.x) {
        int p0 = atomicAdd(&cu0[e0[n + i]], 1);
        cs0[p0] = e0[i];
        int p1 = atomicAdd(&cu1[e1[n + i]], 1);
        cs1[p1] = e1[i];
    }
}

// ---------------- GAT softmax: per-dst max/denominator + per-edge weights -----
// warp per destination node, both relations. Writes w[e] (float4 per CSR slot).
__global__ __launch_bounds__(256) void gat_softmax2(
    const float* __restrict__ asA, const float* __restrict__ adA,
    const int* __restrict__ offA, const int* __restrict__ csrA,
    float4* __restrict__ wA,
    const float* __restrict__ asB, const float* __restrict__ adB,
    const int* __restrict__ offB, const int* __restrict__ csrB,
    float4* __restrict__ wB) {
    int gwid = (blockIdx.x * blockDim.x + threadIdx.x) >> 5;
    if (gwid >= 2 * NN) return;
    int rel = gwid >= NN;
    int wid = gwid - rel * NN;
    int lane = threadIdx.x & 31;
    const float* __restrict__ alpha_s = rel ? asB : asA;
    const float* __restrict__ alpha_d = rel ? adB : adA;
    const int* __restrict__ off       = rel ? offB : offA;
    const int* __restrict__ csr       = rel ? csrB : csrA;
    float4* __restrict__ wbuf         = rel ? wB : wA;

    int s = off[wid], e = off[wid + 1];
    float4 ad = *(const float4*)(alpha_d + (size_t)wid * 4);

    float m0 = -3e38f, m1 = -3e38f, m2 = -3e38f, m3 = -3e38f;
    for (int i = s + lane; i < e; i += 32) {
        int src = csr[i];
        float4 as = *(const float4*)(alpha_s + (size_t)src * 4);
        m0 = fmaxf(m0, lrelu(as.x + ad.x));
        m1 = fmaxf(m1, lrelu(as.y + ad.y));
        m2 = fmaxf(m2, lrelu(as.z + ad.z));
        m3 = fmaxf(m3, lrelu(as.w + ad.w));
    }
#pragma unroll
    for (int o = 16; o; o >>= 1) {
        m0 = fmaxf(m0, __shfl_xor_sync(FULL, m0, o));
        m1 = fmaxf(m1, __shfl_xor_sync(FULL, m1, o));
        m2 = fmaxf(m2, __shfl_xor_sync(FULL, m2, o));
        m3 = fmaxf(m3, __shfl_xor_sync(FULL, m3, o));
    }
    float s0 = 0.f, s1 = 0.f, s2 = 0.f, s3 = 0.f;
    for (int i = s + lane; i < e; i += 32) {
        int src = csr[i];
        float4 as = *(const float4*)(alpha_s + (size_t)src * 4);
        s0 += __expf(lrelu(as.x + ad.x) - m0);
        s1 += __expf(lrelu(as.y + ad.y) - m1);
        s2 += __expf(lrelu(as.z + ad.z) - m2);
        s3 += __expf(lrelu(as.w + ad.w) - m3);
    }
#pragma unroll
    for (int o = 16; o; o >>= 1) {
        s0 += __shfl_xor_sync(FULL, s0, o);
        s1 += __shfl_xor_sync(FULL, s1, o);
        s2 += __shfl_xor_sync(FULL, s2, o);
        s3 += __shfl_xor_sync(FULL, s3, o);
    }
    float inv0 = 1.f / (s0 + 1e-16f), inv1 = 1.f / (s1 + 1e-16f);
    float inv2 = 1.f / (s2 + 1e-16f), inv3 = 1.f / (s3 + 1e-16f);

    for (int i = s + lane; i < e; i += 32) {
        int src = csr[i];
        float4 as = *(const float4*)(alpha_s + (size_t)src * 4);
        float4 w;
        w.x = __expf(lrelu(as.x + ad.x) - m0) * inv0;
        w.y = __expf(lrelu(as.y + ad.y) - m1) * inv1;
        w.z = __expf(lrelu(as.z + ad.z) - m2) * inv2;
        w.w = __expf(lrelu(as.w + ad.w) - m3) * inv3;
        wbuf[i] = w;
    }
}

// ---------------- GAT gather: weighted aggregation + bias + ELU ----------------
// warp per destination node; 4 edge-groups x 8 lanes. Lane owns 16 channels
// (= half a head -> single scalar weight per lane per edge). No shfl in loop.
__global__ __launch_bounds__(256) void gat_gather2(
    const __half* __restrict__ hsA, const float* __restrict__ wA,
    const int* __restrict__ offA, const int* __restrict__ csrA,
    const float* __restrict__ bA, float* __restrict__ oA,
    const __half* __restrict__ hsB, const float* __restrict__ wB,
    const int* __restrict__ offB, const int* __restrict__ csrB,
    const float* __restrict__ bB, float* __restrict__ oB) {
    int gwid = (blockIdx.x * blockDim.x + threadIdx.x) >> 5;
    if (gwid >= 2 * NN) return;
    int rel = gwid >= NN;
    int wid = gwid - rel * NN;
    int lane = threadIdx.x & 31;
    const __half* __restrict__ hs   = rel ? hsB : hsA;
    const float* __restrict__ wbuf  = rel ? wB : wA;
    const int* __restrict__ off     = rel ? offB : offA;
    const int* __restrict__ csr     = rel ? csrB : csrA;
    const float* __restrict__ bias  = rel ? bB : bA;
    float* __restrict__ out         = rel ? oB : oA;

    int lw = lane & 7;          // lane within group
    int g  = lane >> 3;         // edge group 0..3
    int head = lw >> 1;         // channels [lw*16, lw*16+16) -> head lw/2

    int s = off[wid], e = off[wid + 1];
    const uint4* hsb = (const uint4*)hs;   // 16 uint4 per 128-ch row

    float acc[16];
#pragma unroll
    for (int t = 0; t < 16; t++) acc[t] = 0.f;

    for (int i = s + g; i < e; i += 4) {
        int src = csr[i];                       // broadcast within group
        float w = wbuf[(size_t)i * 4 + head];
        uint4 v0 = hsb[(size_t)src * 16 + lw * 2];
        uint4 v1 = hsb[(size_t)src * 16 + lw * 2 + 1];
        const __half2* h0 = (const __half2*)&v0;
        const __half2* h1 = (const __half2*)&v1;
#pragma unroll
        for (int q = 0; q < 4; q++) {
            float2 f0 = __half22float2(h0[q]);
            float2 f1 = __half22float2(h1[q]);
            acc[2 * q]     += w * f0.x;
            acc[2 * q + 1] += w * f0.y;
            acc[8 + 2 * q]     += w * f1.x;
            acc[8 + 2 * q + 1] += w * f1.y;
        }
    }
    // combine the 4 edge-groups
#pragma unroll
    for (int t = 0; t < 16; t++) {
        acc[t] += __shfl_xor_sync(FULL, acc[t], 8);
        acc[t] += __shfl_xor_sync(FULL, acc[t], 16);
    }
    if (g == 0) {
        int cb = lw * 16;
        float* op = out + (size_t)wid * DD + cb;
        const float* bp = bias + cb;
#pragma unroll
        for (int q = 0; q < 4; q++) {
            float4 bv = *(const float4*)(bp + 4 * q);
            float4 o;
            o.x = eluf(acc[4 * q]     + bv.x);
            o.y = eluf(acc[4 * q + 1] + bv.y);
            o.z = eluf(acc[4 * q + 2] + bv.z);
            o.w = eluf(acc[4 * q + 3] + bv.w);
            *(float4*)(op + 4 * q) = o;
        }
    }
}

// ---------------- host orchestration ----------------
extern "C" void kernel_launch(void* const* d_in, const int* in_sizes, int n_in,
                              void* d_out, int out_size) {
    (void)in_sizes; (void)n_in; (void)out_size;
    const float* x_food     = (const float*)d_in[0];
    const float* x_nut      = (const float*)d_in[1];
    const float* Wsrc_fn    = (const float*)d_in[2];
    const float* Wdst_fn    = (const float*)d_in[3];
    const float* att_src_fn = (const float*)d_in[4];
    const float* att_dst_fn = (const float*)d_in[5];
    const float* bias_fn    = (const float*)d_in[6];
    const float* Wsrc_nf    = (const float*)d_in[7];
    const float* Wdst_nf    = (const float*)d_in[8];
    const float* att_src_nf = (const float*)d_in[9];
    const float* att_dst_nf = (const float*)d_in[10];
    const float* bias_nf    = (const float*)d_in[11];
    const int*   ei_fn      = (const int*)d_in[12];
    const int*   ei_nf      = (const int*)d_in[13];
    float* out = (float*)d_out;

    __half *hs0, *hs1;
    float *hf, *hn, *as0, *as1, *ad0, *ad1, *Ad0, *Ad1, *w0, *w1;
    int *off0, *off1, *cur0, *cur1, *csr0, *csr1;
    cudaGetSymbolAddress((void**)&hs0,  g_hs0);
    cudaGetSymbolAddress((void**)&hs1,  g_hs1);
    cudaGetSymbolAddress((void**)&hf,   g_hfood);
    cudaGetSymbolAddress((void**)&hn,   g_hnut);
    cudaGetSymbolAddress((void**)&as0,  g_as0);
    cudaGetSymbolAddress((void**)&as1,  g_as1);
    cudaGetSymbolAddress((void**)&ad0,  g_ad0);
    cudaGetSymbolAddress((void**)&ad1,  g_ad1);
    cudaGetSymbolAddress((void**)&Ad0,  g_Ad0);
    cudaGetSymbolAddress((void**)&Ad1,  g_Ad1);
    cudaGetSymbolAddress((void**)&w0,   g_w0);
    cudaGetSymbolAddress((void**)&w1,   g_w1);
    cudaGetSymbolAddress((void**)&off0, g_off0);
    cudaGetSymbolAddress((void**)&off1, g_off1);
    cudaGetSymbolAddress((void**)&cur0, g_cur0);
    cudaGetSymbolAddress((void**)&cur1, g_cur1);
    cudaGetSymbolAddress((void**)&csr0, g_csr0);
    cudaGetSymbolAddress((void**)&csr1, g_csr1);

    int gblocks = (NN + 127) / 128;
    int ablocks = (NN * 32 + 255) / 256;
    int aggblocks = (2 * NN * 32 + 255) / 256;

    // launch order keeps the ncu-profiled index-3 launch = gemm_fused
    avec2<<<2, 128>>>(Wdst_fn, Wdst_nf, att_dst_fn, att_dst_nf, Ad0, Ad1);   // 0
    zero2<<<196, 256>>>(off0, off1, NN + 1);                                  // 1
    hist2<<<512, 256>>>(ei_fn + EE, ei_nf + EE, off0, off1, EE);              // 2
    gemm_fused<<<dim3(gblocks, 2), 256>>>(                                    // 3 (profiled)
        x_food, x_nut, Wsrc_fn, Wsrc_nf, att_src_fn, att_src_nf,
        hs0, hs1, as0, as1);
    alpha2<<<dim3(ablocks, 2), 256>>>(x_nut, x_food, Ad0, Ad1, ad0, ad1);     // 4
    scan2<<<2, 1024>>>(off0, off1, cur0, cur1, NN + 1);                       // 5
    fill2<<<512, 256>>>(ei_fn, ei_nf, cur0, cur1, csr0, csr1, EE);            // 6
    gat_softmax2<<<aggblocks, 256>>>(                                         // 7
        as0, ad0, off0, csr0, (float4*)w0,
        as1, ad1, off1, csr1, (float4*)w1);
    gat_gather2<<<aggblocks, 256>>>(                                          // 8
        hs0, w0, off0, csr0, bias_fn, hn,
        hs1, w1, off1, csr1, bias_nf, hf);

    // layer 2
    avec2<<<2, 128>>>(Wdst_fn + DD * DD, Wdst_nf + DD * DD,
                      att_dst_fn + DD, att_dst_nf + DD, Ad0, Ad1);            // 9
    gemm_fused<<<dim3(gblocks, 2), 256>>>(                                    // 10
        hf, hn, Wsrc_fn + DD * DD, Wsrc_nf + DD * DD,
        att_src_fn + DD, att_src_nf + DD, hs0, hs1, as0, as1);
    alpha2<<<dim3(ablocks, 2), 256>>>(hn, hf, Ad0, Ad1, ad0, ad1);            // 11
    gat_softmax2<<<aggblocks, 256>>>(                                         // 12
        as0, ad0, off0, csr0, (float4*)w0,
        as1, ad1, off1, csr1, (float4*)w1);
    gat_gather2<<<aggblocks, 256>>>(                                          // 13
        hs0, w0, off0, csr0, bias_fn + DD, out + (size_t)NN * DD,
        hs1, w1, off1, csr1, bias_nf + DD, out);
}